// round 8
// baseline (speedup 1.0000x reference)
#include <cuda_runtime.h>
#include <cstdint>
#include <cstddef>

// GroupedLinearsAdvanced: out[b,o,d] = sum_i x[b,i,d] * W[d,i,o] + bias[d,o]
//   x:    [16, 128, 4096] fp32
//   W:    [4096, 128, 128] fp32   (256 MB, streamed once -> HBM bound)
//   bias: [4096, 128] fp32
//   out:  [16, 128, 4096] fp32
//
// R7: back to the R5 geometry (best so far), but the W stream is staged
// through smem with cp.async (LDGSTS) in an 8-slot ring, 7 iterations of
// lookahead. In-flight W bytes per SM rise from ~2KB/warp (register ring,
// scoreboard-coupled) to 64KB/SM (fire-and-forget), which is what DRAM
// saturation needs. Inner f32x2 loop and output transpose unchanged.

#define B_SZ     16
#define IN_D     128
#define OUT_D    128
#define D_TOT    4096
#define D_TILE   4
#define THREADS  128
#define NSLOT    8                         // smem W ring slots
#define LOOKA    7                         // issue distance (< NSLOT)
#define XS_STRIDE 72                       // floats per i-row: 4*16 + 8 pad
#define X_FLOATS  (IN_D * XS_STRIDE)       // 9216 floats = 36864 B
#define WOFF      X_FLOATS                 // W ring starts here
#define W_SLOT_F  (D_TILE * OUT_D)         // 512 floats per slot
#define SMEM_FLOATS (X_FLOATS + NSLOT * W_SLOT_F)   // 13312 floats
#define SMEM_BYTES  (SMEM_FLOATS * 4)               // 53248 B

__device__ __forceinline__ void cp_async16(uint32_t smem_dst, const void* gsrc) {
    asm volatile("cp.async.cg.shared.global [%0], [%1], 16;"
                 :: "r"(smem_dst), "l"(gsrc) : "memory");
}
__device__ __forceinline__ void cp_commit() {
    asm volatile("cp.async.commit_group;" ::: "memory");
}
__device__ __forceinline__ void cp_wait7() {
    asm volatile("cp.async.wait_group 7;" ::: "memory");
}

__global__ void __launch_bounds__(THREADS, 4)
grouped_linears_kernel(const float* __restrict__ x,
                       const float* __restrict__ W,
                       const float* __restrict__ bias,
                       float* __restrict__ out)
{
    extern __shared__ float sm[];   // [0,X_FLOATS): x tile / out transpose
                                    // [WOFF, +NSLOT*512): W ring

    const int tid  = threadIdx.x;
    const int warp = tid >> 5;      // 0..3, one d-channel per warp
    const int lane = tid & 31;
    const int d0   = blockIdx.x * D_TILE;
    const int d    = d0 + warp;

    const uint32_t smem_u32 = (uint32_t)__cvta_generic_to_shared(sm);
    // this lane's smem W base within a slot (floats): warp*128 + 4*lane
    const uint32_t wslot_lane_b =
        smem_u32 + (WOFF + warp * OUT_D + 4 * lane) * 4;
    // this lane's gmem W base: W[d][0][4*lane]
    const float* wg = W + (size_t)d * IN_D * OUT_D + 4 * lane;

    // ---------------- Prologue: launch W prefetch pipeline first ----------------
#pragma unroll
    for (int s = 0; s < LOOKA; ++s) {
        cp_async16(wslot_lane_b + (uint32_t)(s * W_SLOT_F * 4), wg + s * OUT_D);
        cp_commit();
    }

    // bias early too
    float4 bv = *reinterpret_cast<const float4*>(bias + (size_t)d * OUT_D + 4 * lane);

    // ---------------- Phase 0: load x tile ----------------
    // sm[i*XS_STRIDE + c*16 + b] = x[b][i][d0+c]; 16 float4 per thread.
#pragma unroll
    for (int r = 0; r < 16; ++r) {
        int p = tid + r * THREADS;      // 0..2047
        int i = p >> 4;
        int b = p & 15;
        float4 v = *reinterpret_cast<const float4*>(
            x + ((size_t)b * IN_D + i) * D_TOT + d0);
        float* row = &sm[i * XS_STRIDE + b];
        row[0 * 16] = v.x; row[1 * 16] = v.y; row[2 * 16] = v.z; row[3 * 16] = v.w;
    }
    __syncthreads();

    // ---------------- Phase 1: main GEMM loop ----------------
    // acc2[k][j]: packed f32x2 accumulator for (b=2k lo, b=2k+1 hi), o = 4*lane + j.
    unsigned long long acc2[8][4];
    {
        float bj[4] = {bv.x, bv.y, bv.z, bv.w};
#pragma unroll
        for (int j = 0; j < 4; ++j) {
            unsigned long long pk;
            asm("mov.b64 %0, {%1, %1};" : "=l"(pk) : "f"(bj[j]));
#pragma unroll
            for (int k = 0; k < 8; ++k) acc2[k][j] = pk;
        }
    }

#pragma unroll 4
    for (int i = 0; i < IN_D; ++i) {
        // Refill LOOKA ahead. Tail: clamp to last row -> idempotent rewrite
        // of the same bytes, keeps the group count uniform for wait_group.
        int ipf  = i + LOOKA; if (ipf > IN_D - 1) ipf = IN_D - 1;
        cp_async16(wslot_lane_b + (uint32_t)((ipf & (NSLOT - 1)) * W_SLOT_F * 4),
                   wg + ipf * OUT_D);
        cp_commit();
        cp_wait7();                 // slot i is now resident

        // W for this (i, d, lane): one conflict-free LDS.128
        float4 wcur = *reinterpret_cast<const float4*>(
            &sm[WOFF + (i & (NSLOT - 1)) * W_SLOT_F + warp * OUT_D + 4 * lane]);

        // x pairs for this (i, d): 16 floats = 4x LDS.128, all lanes broadcast
        const double2* xr =
            reinterpret_cast<const double2*>(&sm[i * XS_STRIDE + warp * 16]);
        double2 a0 = xr[0], a1 = xr[1], a2 = xr[2], a3 = xr[3];
        unsigned long long x2[8];
        x2[0] = __double_as_longlong(a0.x); x2[1] = __double_as_longlong(a0.y);
        x2[2] = __double_as_longlong(a1.x); x2[3] = __double_as_longlong(a1.y);
        x2[4] = __double_as_longlong(a2.x); x2[5] = __double_as_longlong(a2.y);
        x2[6] = __double_as_longlong(a3.x); x2[7] = __double_as_longlong(a3.y);

        // duplicate W scalars into both f32x2 halves
        unsigned long long wd[4];
        asm("mov.b64 %0, {%1, %1};" : "=l"(wd[0]) : "f"(wcur.x));
        asm("mov.b64 %0, {%1, %1};" : "=l"(wd[1]) : "f"(wcur.y));
        asm("mov.b64 %0, {%1, %1};" : "=l"(wd[2]) : "f"(wcur.z));
        asm("mov.b64 %0, {%1, %1};" : "=l"(wd[3]) : "f"(wcur.w));

#pragma unroll
        for (int k = 0; k < 8; ++k) {
#pragma unroll
            for (int j = 0; j < 4; ++j) {
                asm("fma.rn.f32x2 %0, %1, %2, %0;"
                    : "+l"(acc2[k][j]) : "l"(x2[k]), "l"(wd[j]));
            }
        }
    }

    // ---------------- Phase 2: transpose through smem ----------------
    __syncthreads();   // done reading x tile (outs reuses the x region only)
    // outs[c][b*128 + o], c = warp (0..3)
    float* outs = sm;
#pragma unroll
    for (int k = 0; k < 8; ++k) {
#pragma unroll
        for (int j = 0; j < 4; ++j) {
            float lo, hi;
            asm("mov.b64 {%0, %1}, %2;" : "=f"(lo), "=f"(hi) : "l"(acc2[k][j]));
            int o = 4 * lane + j;
            outs[warp * 2048 + (2 * k)     * 128 + o] = lo;
            outs[warp * 2048 + (2 * k + 1) * 128 + o] = hi;
        }
    }
    __syncthreads();

    // ---------------- Phase 3: coalesced global store ----------------
    // Each (b,o) pair p gets a 4-float d-contiguous run (one float4; the
    // adjacent-d0 CTA fills the sector's other half, merged in L2).
#pragma unroll
    for (int r = 0; r < 4; ++r) {
        int p4 = 4 * (tid + r * THREADS);   // groups of 4 consecutive p
        float v[D_TILE][4];
#pragma unroll
        for (int c = 0; c < D_TILE; ++c) {
            float4 t4 = *reinterpret_cast<float4*>(&outs[c * 2048 + p4]);
            v[c][0] = t4.x; v[c][1] = t4.y; v[c][2] = t4.z; v[c][3] = t4.w;
        }
#pragma unroll
        for (int pp = 0; pp < 4; ++pp) {
            int p = p4 + pp;            // p = b*128 + o
            float* op = out + (size_t)p * D_TOT + d0;
            *reinterpret_cast<float4*>(op) =
                make_float4(v[0][pp], v[1][pp], v[2][pp], v[3][pp]);
        }
    }
}

extern "C" void kernel_launch(void* const* d_in, const int* in_sizes, int n_in,
                              void* d_out, int out_size)
{
    (void)in_sizes; (void)n_in; (void)out_size;
    const float* x    = (const float*)d_in[0];
    const float* W    = (const float*)d_in[1];
    const float* bias = (const float*)d_in[2];
    float*       out  = (float*)d_out;

    // Idempotent, host-side, not a stream op: safe under graph capture.
    cudaFuncSetAttribute(grouped_linears_kernel,
                         cudaFuncAttributeMaxDynamicSharedMemorySize, SMEM_BYTES);

    grouped_linears_kernel<<<D_TOT / D_TILE, THREADS, SMEM_BYTES>>>(x, W, bias, out);
}